// round 1
// baseline (speedup 1.0000x reference)
#include <cuda_runtime.h>
#include <mma.h>
#include <cstring>

using namespace nvcuda;

#define CB   8
#define CT   1024
#define CC   1024
#define CNH  16
#define CHD  64
#define CFF  4096
#define CM   (CB*CT)   // 8192 rows

// ---------------- scratch (static device arrays; no allocations allowed) ----
__device__ float g_h[(size_t)CM * CC];                    // 32 MB  (LN1 out, reused for LN2 out)
__device__ float g_qkv[(size_t)CM * 3 * CC];              // 96 MB
__device__ float g_scores[(size_t)CB * CNH * CT * CT];    // 512 MB
__device__ float g_y[(size_t)CM * CC];                    // 32 MB
__device__ float g_ff[(size_t)CM * CFF];                  // 128 MB

// ---------------- generic batched tf32 WMMA GEMM ---------------------------
// C = alpha * A@B (+bias) (+residual) (relu?)   A:[M,K] row-major
// B row-major [K,N], or (bcol=1) col-major access B[k,n] = Bptr[n*ldb + k]
// batch index z decomposed: zo = z/inner, zi = z%inner; offsets via (sXo,sXi)

struct GP {
  const float* A; long long lda, sAo, sAi;
  const float* B; long long ldb, sBo, sBi;
  float*       C; long long ldc, sCo, sCi;
  const float* R; long long ldr, sRo, sRi;   // residual (nullable)
  const float* bias;                          // length N (nullable)
  int M, N, K;
  float alpha;
  int relu;
  int bcol;
  int inner;
};

#define BM 128
#define BN 128
#define BK 32

__global__ __launch_bounds__(256) void gemm_tf32(GP p) {
  __shared__ float As[BM][BK];
  __shared__ float Bs[BK][BN];
  __shared__ float Cw[8][256];

  const int z  = blockIdx.z;
  const int zo = z / p.inner, zi = z % p.inner;
  const float* A  = p.A + (size_t)zo * p.sAo + (size_t)zi * p.sAi;
  const float* Bg = p.B + (size_t)zo * p.sBo + (size_t)zi * p.sBi;
  float*       Cg = p.C + (size_t)zo * p.sCo + (size_t)zi * p.sCi;
  const float* Rg = p.R ? (p.R + (size_t)zo * p.sRo + (size_t)zi * p.sRi) : nullptr;

  const int m0 = blockIdx.y * BM;
  const int n0 = blockIdx.x * BN;
  const int tid  = threadIdx.x;
  const int warp = tid >> 5, lane = tid & 31;
  const int wm = warp & 1;       // 0..1  -> 64 rows each
  const int wn = warp >> 1;      // 0..3  -> 32 cols each

  wmma::fragment<wmma::accumulator, 16, 16, 8, float> acc[4][2];
#pragma unroll
  for (int i = 0; i < 4; i++)
#pragma unroll
    for (int j = 0; j < 2; j++) wmma::fill_fragment(acc[i][j], 0.0f);

  for (int k0 = 0; k0 < p.K; k0 += BK) {
    // stage A tile (coalesced: 32 consecutive cols per row)
#pragma unroll 4
    for (int i = tid; i < BM * BK; i += 256) {
      int r = i >> 5, c = i & 31;
      int gr = m0 + r;
      As[r][c] = (gr < p.M) ? A[(size_t)gr * p.lda + (k0 + c)] : 0.0f;
    }
    // stage B tile
    if (!p.bcol) {
#pragma unroll 4
      for (int i = tid; i < BK * BN; i += 256) {
        int r = i >> 7, c = i & 127;
        int gc = n0 + c;
        Bs[r][c] = (gc < p.N) ? Bg[(size_t)(k0 + r) * p.ldb + gc] : 0.0f;
      }
    } else {
#pragma unroll 4
      for (int i = tid; i < BK * BN; i += 256) {
        int c = i >> 5, r = i & 31;          // consecutive threads -> consecutive k (coalesced)
        int gc = n0 + c;
        Bs[r][c] = (gc < p.N) ? Bg[(size_t)gc * p.ldb + (k0 + r)] : 0.0f;
      }
    }
    __syncthreads();

#pragma unroll
    for (int ks = 0; ks < BK / 8; ks++) {
      wmma::fragment<wmma::matrix_a, 16, 16, 8, wmma::precision::tf32, wmma::row_major> af[4];
      wmma::fragment<wmma::matrix_b, 16, 16, 8, wmma::precision::tf32, wmma::row_major> bf[2];
#pragma unroll
      for (int i = 0; i < 4; i++) {
        wmma::load_matrix_sync(af[i], &As[wm * 64 + i * 16][ks * 8], BK);
#pragma unroll
        for (int t = 0; t < af[i].num_elements; t++)
          af[i].x[t] = wmma::__float_to_tf32(af[i].x[t]);
      }
#pragma unroll
      for (int j = 0; j < 2; j++) {
        wmma::load_matrix_sync(bf[j], &Bs[ks * 8][wn * 32 + j * 16], BN);
#pragma unroll
        for (int t = 0; t < bf[j].num_elements; t++)
          bf[j].x[t] = wmma::__float_to_tf32(bf[j].x[t]);
      }
#pragma unroll
      for (int i = 0; i < 4; i++)
#pragma unroll
        for (int j = 0; j < 2; j++)
          wmma::mma_sync(acc[i][j], af[i], bf[j], acc[i][j]);
    }
    __syncthreads();
  }

  // epilogue: per-fragment via per-warp smem tile
#pragma unroll
  for (int i = 0; i < 4; i++) {
#pragma unroll
    for (int j = 0; j < 2; j++) {
      wmma::store_matrix_sync(&Cw[warp][0], acc[i][j], 16, wmma::mem_row_major);
      __syncwarp();
      const int r0 = m0 + wm * 64 + i * 16;
      const int c0 = n0 + wn * 32 + j * 16;
      const int rr = lane >> 1;
      const int cbase = (lane & 1) * 8;
#pragma unroll
      for (int e = 0; e < 8; e++) {
        int cc = cbase + e;
        int gr = r0 + rr, gc = c0 + cc;
        if (gr < p.M && gc < p.N) {
          float v = Cw[warp][rr * 16 + cc] * p.alpha;
          if (p.bias) v += p.bias[gc];
          if (Rg)     v += Rg[(size_t)gr * p.ldr + gc];
          if (p.relu) v = fmaxf(v, 0.0f);
          Cg[(size_t)gr * p.ldc + gc] = v;
        }
      }
      __syncwarp();
    }
  }
}

// ---------------- layernorm -------------------------------------------------
__global__ __launch_bounds__(256) void ln_kernel(const float* __restrict__ x,
                                                 const float* __restrict__ g,
                                                 const float* __restrict__ bt,
                                                 float* __restrict__ o) {
  const int row = blockIdx.x;
  const int tid = threadIdx.x;
  const float4* xr = (const float4*)(x + (size_t)row * CC);
  float4 v = xr[tid];
  float s  = v.x + v.y + v.z + v.w;
  float ss = v.x * v.x + v.y * v.y + v.z * v.z + v.w * v.w;

  __shared__ float ra[8], rb[8];
#pragma unroll
  for (int off = 16; off; off >>= 1) {
    s  += __shfl_xor_sync(0xFFFFFFFFu, s, off);
    ss += __shfl_xor_sync(0xFFFFFFFFu, ss, off);
  }
  if ((tid & 31) == 0) { ra[tid >> 5] = s; rb[tid >> 5] = ss; }
  __syncthreads();
  s = 0.f; ss = 0.f;
#pragma unroll
  for (int w = 0; w < 8; w++) { s += ra[w]; ss += rb[w]; }

  const float mean = s * (1.0f / CC);
  const float var  = ss * (1.0f / CC) - mean * mean;
  const float rstd = rsqrtf(var + 1e-5f);

  float4 gg = ((const float4*)g)[tid];
  float4 bb = ((const float4*)bt)[tid];
  float4 r;
  r.x = (v.x - mean) * rstd * gg.x + bb.x;
  r.y = (v.y - mean) * rstd * gg.y + bb.y;
  r.z = (v.z - mean) * rstd * gg.z + bb.z;
  r.w = (v.w - mean) * rstd * gg.w + bb.w;
  ((float4*)(o + (size_t)row * CC))[tid] = r;
}

// ---------------- masked softmax (key-padding, in place) --------------------
__global__ __launch_bounds__(128) void softmax_kernel(float* __restrict__ sc,
                                                      const int* __restrict__ seq_ls) {
  const int row = blockIdx.x;            // b*NH*T + h*T + q
  const int b   = row >> 14;             // / (NH*T) = 16384
  const int seq = seq_ls[b];
  float* p = sc + (size_t)row * CT;
  const int tid = threadIdx.x;
  __shared__ float red[4];

  float m = -1e30f;
  for (int j = tid; j < seq; j += 128) m = fmaxf(m, p[j]);
#pragma unroll
  for (int off = 16; off; off >>= 1) m = fmaxf(m, __shfl_xor_sync(0xFFFFFFFFu, m, off));
  if ((tid & 31) == 0) red[tid >> 5] = m;
  __syncthreads();
  m = fmaxf(fmaxf(red[0], red[1]), fmaxf(red[2], red[3]));
  __syncthreads();

  float s = 0.0f;
  for (int j = tid; j < seq; j += 128) {
    float e = __expf(p[j] - m);
    p[j] = e;
    s += e;
  }
#pragma unroll
  for (int off = 16; off; off >>= 1) s += __shfl_xor_sync(0xFFFFFFFFu, s, off);
  if ((tid & 31) == 0) red[tid >> 5] = s;
  __syncthreads();
  s = red[0] + red[1] + red[2] + red[3];
  const float inv = 1.0f / s;
  for (int j = tid; j < CT; j += 128) p[j] = (j < seq) ? p[j] * inv : 0.0f;
}

// ---------------- launch ----------------------------------------------------
static GP zero_gp() { GP p; memset(&p, 0, sizeof(p)); p.inner = 1; p.alpha = 1.0f; return p; }

extern "C" void kernel_launch(void* const* d_in, const int* in_sizes, int n_in,
                              void* d_out, int out_size) {
  (void)in_sizes; (void)n_in; (void)out_size;
  const float* x      = (const float*)d_in[0];
  const int*   seq_ls = (const int*)  d_in[1];
  const float* ln1_g  = (const float*)d_in[2];
  const float* ln1_b  = (const float*)d_in[3];
  const float* w_qkv  = (const float*)d_in[4];
  const float* b_qkv  = (const float*)d_in[5];
  const float* w_proj = (const float*)d_in[6];
  const float* b_proj = (const float*)d_in[7];
  const float* ln2_g  = (const float*)d_in[8];
  const float* ln2_b  = (const float*)d_in[9];
  const float* w_fc   = (const float*)d_in[10];
  const float* b_fc   = (const float*)d_in[11];
  const float* w_fc2  = (const float*)d_in[12];
  const float* b_fc2  = (const float*)d_in[13];
  float* out = (float*)d_out;

  float *h, *qkv, *sc, *y, *ff;
  cudaGetSymbolAddress((void**)&h,   g_h);
  cudaGetSymbolAddress((void**)&qkv, g_qkv);
  cudaGetSymbolAddress((void**)&sc,  g_scores);
  cudaGetSymbolAddress((void**)&y,   g_y);
  cudaGetSymbolAddress((void**)&ff,  g_ff);

  // 1) LN1
  ln_kernel<<<CM, 256>>>(x, ln1_g, ln1_b, h);

  // 2) QKV = h @ w_qkv + b_qkv          [8192,1024]x[1024,3072]
  {
    GP p = zero_gp();
    p.A = h;     p.lda = CC;
    p.B = w_qkv; p.ldb = 3 * CC;
    p.C = qkv;   p.ldc = 3 * CC;
    p.M = CM; p.N = 3 * CC; p.K = CC;
    p.bias = b_qkv;
    gemm_tf32<<<dim3(24, 64, 1), 256>>>(p);
  }

  // 3) scores = (Q @ K^T) / 8           batched over (b,h): [1024,64]x[64,1024]
  {
    GP p = zero_gp();
    p.A = qkv;      p.lda = 3 * CC; p.sAo = (long long)CT * 3 * CC; p.sAi = CHD;
    p.B = qkv + CC; p.ldb = 3 * CC; p.sBo = (long long)CT * 3 * CC; p.sBi = CHD;
    p.bcol = 1;
    p.C = sc; p.ldc = CT; p.sCo = (long long)CNH * CT * CT; p.sCi = (long long)CT * CT;
    p.M = CT; p.N = CT; p.K = CHD;
    p.alpha = 0.125f;   // 1/sqrt(64)
    p.inner = CNH;
    gemm_tf32<<<dim3(8, 8, CB * CNH), 256>>>(p);
  }

  // 4) masked softmax (in place)
  softmax_kernel<<<CB * CNH * CT, 128>>>(sc, seq_ls);

  // 5) Y = P @ V                        batched: [1024,1024]x[1024,64]
  {
    GP p = zero_gp();
    p.A = sc;           p.lda = CT;     p.sAo = (long long)CNH * CT * CT; p.sAi = (long long)CT * CT;
    p.B = qkv + 2 * CC; p.ldb = 3 * CC; p.sBo = (long long)CT * 3 * CC;   p.sBi = CHD;
    p.C = y; p.ldc = CC; p.sCo = (long long)CT * CC; p.sCi = CHD;
    p.M = CT; p.N = CHD; p.K = CT;
    p.inner = CNH;
    gemm_tf32<<<dim3(1, 8, CB * CNH), 256>>>(p);
  }

  // 6) x1 = x + Y @ w_proj + b_proj  -> out
  {
    GP p = zero_gp();
    p.A = y;      p.lda = CC;
    p.B = w_proj; p.ldb = CC;
    p.C = out;    p.ldc = CC;
    p.M = CM; p.N = CC; p.K = CC;
    p.bias = b_proj;
    p.R = x; p.ldr = CC;
    gemm_tf32<<<dim3(8, 64, 1), 256>>>(p);
  }

  // 7) LN2
  ln_kernel<<<CM, 256>>>(out, ln2_g, ln2_b, h);

  // 8) ff = relu(h @ w_fc + b_fc)       [8192,1024]x[1024,4096]
  {
    GP p = zero_gp();
    p.A = h;    p.lda = CC;
    p.B = w_fc; p.ldb = CFF;
    p.C = ff;   p.ldc = CFF;
    p.M = CM; p.N = CFF; p.K = CC;
    p.bias = b_fc; p.relu = 1;
    gemm_tf32<<<dim3(32, 64, 1), 256>>>(p);
  }

  // 9) out = out + ff @ w_fc2 + b_fc2   [8192,4096]x[4096,1024]
  {
    GP p = zero_gp();
    p.A = ff;    p.lda = CFF;
    p.B = w_fc2; p.ldb = CC;
    p.C = out;   p.ldc = CC;
    p.M = CM; p.N = CC; p.K = CFF;
    p.bias = b_fc2;
    p.R = out; p.ldr = CC;
    gemm_tf32<<<dim3(8, 64, 1), 256>>>(p);
  }
}

// round 2
// speedup vs baseline: 1.9426x; 1.9426x over previous
#include <cuda_runtime.h>
#include <mma.h>
#include <cstring>

using namespace nvcuda;

#define CB   8
#define CT   1024
#define CC   1024
#define CNH  16
#define CHD  64
#define CFF  4096
#define CM   (CB*CT)   // 8192 rows

// ---------------- scratch (static device arrays; no allocations allowed) ----
__device__ float g_h[(size_t)CM * CC];                    // 32 MB
__device__ float g_qkv[(size_t)CM * 3 * CC];              // 96 MB
__device__ float g_scores[(size_t)CB * CNH * CT * CT];    // 512 MB
__device__ float g_y[(size_t)CM * CC];                    // 32 MB
__device__ float g_ff[(size_t)CM * CFF];                  // 128 MB

// ---------------- generic batched tf32 WMMA GEMM (cp.async pipelined) -------
struct GP {
  const float* A; long long lda, sAo, sAi;
  const float* B; long long ldb, sBo, sBi;
  float*       C; long long ldc, sCo, sCi;
  const float* R; long long ldr, sRo, sRi;   // residual (nullable)
  const float* bias;                          // length N (nullable)
  int M, N, K;
  float alpha;
  int relu;
  int inner;
};

#define BM 128
#define BN 128
#define BK 32
#define AKPAD 36
#define BNPAD 132
#define BKPAD 36

// per-stage float counts
#define ASZ   (BM * AKPAD)                 // 4608
#define BSZ_R (BK * BNPAD)                 // 4224
#define BSZ_C (BN * BKPAD)                 // 4608
#define STAGE (ASZ + BSZ_C)                // 9216 floats (max of both layouts)
#define GEMM_SMEM_BYTES (2 * STAGE * 4)    // 73728

__device__ __forceinline__ void cp16(float* dst, const float* src, bool valid) {
  unsigned sa = (unsigned)__cvta_generic_to_shared(dst);
  int sz = valid ? 16 : 0;
  asm volatile("cp.async.cg.shared.global [%0], [%1], 16, %2;\n"
               :: "r"(sa), "l"(src), "r"(sz));
}
__device__ __forceinline__ void cp_commit() {
  asm volatile("cp.async.commit_group;\n" ::);
}
__device__ __forceinline__ void cp_wait0() {
  asm volatile("cp.async.wait_group 0;\n" ::);
}

template <int BCOL>
__global__ __launch_bounds__(256, 2) void gemm_tf32(GP p) {
  extern __shared__ float sm[];
  __shared__ float Cw[8][256];

  const int z  = blockIdx.z;
  const int zo = z / p.inner, zi = z % p.inner;
  const float* A  = p.A + (size_t)zo * p.sAo + (size_t)zi * p.sAi;
  const float* Bg = p.B + (size_t)zo * p.sBo + (size_t)zi * p.sBi;
  float*       Cg = p.C + (size_t)zo * p.sCo + (size_t)zi * p.sCi;
  const float* Rg = p.R ? (p.R + (size_t)zo * p.sRo + (size_t)zi * p.sRi) : nullptr;

  const int m0 = blockIdx.y * BM;
  const int n0 = blockIdx.x * BN;
  const int tid  = threadIdx.x;
  const int warp = tid >> 5, lane = tid & 31;
  const int wm = warp & 1;       // 0..1 -> 64 rows
  const int wn = warp >> 1;      // 0..3 -> 32 cols

  const int niter = p.K / BK;

  // --- stage loaders --------------------------------------------------------
  auto load_stage = [&](int it, int s) {
    float* As = sm + s * STAGE;
    float* Bs = As + ASZ;
    const int k0 = it * BK;
    // A: 128 rows x 8 float4  (1024 chunks / 256 threads = 4 each)
#pragma unroll
    for (int t = 0; t < 4; t++) {
      int i  = tid + t * 256;
      int r  = i >> 3, c4 = i & 7;
      int gr = m0 + r;
      cp16(As + r * AKPAD + c4 * 4,
           A + (size_t)gr * p.lda + k0 + c4 * 4,
           gr < p.M);
    }
    if (!BCOL) {
      // B row-major: 32 rows x 32 float4
#pragma unroll
      for (int t = 0; t < 4; t++) {
        int i  = tid + t * 256;
        int r  = i >> 5, c4 = i & 31;
        int gc = n0 + c4 * 4;
        cp16(Bs + r * BNPAD + c4 * 4,
             Bg + (size_t)(k0 + r) * p.ldb + gc,
             gc < p.N);
      }
    } else {
      // B col-major (contiguous along k): store [BN][BKPAD]
#pragma unroll
      for (int t = 0; t < 4; t++) {
        int i  = tid + t * 256;
        int r  = i >> 3, c4 = i & 7;       // r = n index, c4 = k chunk
        int gc = n0 + r;
        cp16(Bs + r * BKPAD + c4 * 4,
             Bg + (size_t)gc * p.ldb + k0 + c4 * 4,
             gc < p.N);
      }
    }
  };

  wmma::fragment<wmma::accumulator, 16, 16, 8, float> acc[4][2];
#pragma unroll
  for (int i = 0; i < 4; i++)
#pragma unroll
    for (int j = 0; j < 2; j++) wmma::fill_fragment(acc[i][j], 0.0f);

  load_stage(0, 0);
  cp_commit();

  for (int it = 0; it < niter; it++) {
    cp_wait0();
    __syncthreads();
    if (it + 1 < niter) {
      load_stage(it + 1, (it + 1) & 1);
      cp_commit();
    }
    const float* As = sm + (it & 1) * STAGE;
    const float* Bs = As + ASZ;

#pragma unroll
    for (int ks = 0; ks < BK / 8; ks++) {
      wmma::fragment<wmma::matrix_a, 16, 16, 8, wmma::precision::tf32, wmma::row_major> af[4];
#pragma unroll
      for (int i = 0; i < 4; i++) {
        wmma::load_matrix_sync(af[i], As + (wm * 64 + i * 16) * AKPAD + ks * 8, AKPAD);
#pragma unroll
        for (int t = 0; t < af[i].num_elements; t++)
          af[i].x[t] = wmma::__float_to_tf32(af[i].x[t]);
      }
      if (!BCOL) {
        wmma::fragment<wmma::matrix_b, 16, 16, 8, wmma::precision::tf32, wmma::row_major> bf[2];
#pragma unroll
        for (int j = 0; j < 2; j++) {
          wmma::load_matrix_sync(bf[j], Bs + (ks * 8) * BNPAD + wn * 32 + j * 16, BNPAD);
#pragma unroll
          for (int t = 0; t < bf[j].num_elements; t++)
            bf[j].x[t] = wmma::__float_to_tf32(bf[j].x[t]);
        }
#pragma unroll
        for (int i = 0; i < 4; i++)
#pragma unroll
          for (int j = 0; j < 2; j++)
            wmma::mma_sync(acc[i][j], af[i], bf[j], acc[i][j]);
      } else {
        wmma::fragment<wmma::matrix_b, 16, 16, 8, wmma::precision::tf32, wmma::col_major> bf[2];
#pragma unroll
        for (int j = 0; j < 2; j++) {
          wmma::load_matrix_sync(bf[j], Bs + (wn * 32 + j * 16) * BKPAD + ks * 8, BKPAD);
#pragma unroll
          for (int t = 0; t < bf[j].num_elements; t++)
            bf[j].x[t] = wmma::__float_to_tf32(bf[j].x[t]);
        }
#pragma unroll
        for (int i = 0; i < 4; i++)
#pragma unroll
          for (int j = 0; j < 2; j++)
            wmma::mma_sync(acc[i][j], af[i], bf[j], acc[i][j]);
      }
    }
  }

  // ---------------- epilogue ------------------------------------------------
#pragma unroll
  for (int i = 0; i < 4; i++) {
#pragma unroll
    for (int j = 0; j < 2; j++) {
      wmma::store_matrix_sync(&Cw[warp][0], acc[i][j], 16, wmma::mem_row_major);
      __syncwarp();
      const int r0 = m0 + wm * 64 + i * 16;
      const int c0 = n0 + wn * 32 + j * 16;
      const int rr = lane >> 1;
      const int cbase = (lane & 1) * 8;
#pragma unroll
      for (int e = 0; e < 8; e++) {
        int cc = cbase + e;
        int gr = r0 + rr, gc = c0 + cc;
        if (gr < p.M && gc < p.N) {
          float v = Cw[warp][rr * 16 + cc] * p.alpha;
          if (p.bias) v += p.bias[gc];
          if (Rg)     v += Rg[(size_t)gr * p.ldr + gc];
          if (p.relu) v = fmaxf(v, 0.0f);
          Cg[(size_t)gr * p.ldc + gc] = v;
        }
      }
      __syncwarp();
    }
  }
}

// ---------------- layernorm -------------------------------------------------
__global__ __launch_bounds__(256) void ln_kernel(const float* __restrict__ x,
                                                 const float* __restrict__ g,
                                                 const float* __restrict__ bt,
                                                 float* __restrict__ o) {
  const int row = blockIdx.x;
  const int tid = threadIdx.x;
  const float4* xr = (const float4*)(x + (size_t)row * CC);
  float4 v = xr[tid];
  float s  = v.x + v.y + v.z + v.w;
  float ss = v.x * v.x + v.y * v.y + v.z * v.z + v.w * v.w;

  __shared__ float ra[8], rb[8];
#pragma unroll
  for (int off = 16; off; off >>= 1) {
    s  += __shfl_xor_sync(0xFFFFFFFFu, s, off);
    ss += __shfl_xor_sync(0xFFFFFFFFu, ss, off);
  }
  if ((tid & 31) == 0) { ra[tid >> 5] = s; rb[tid >> 5] = ss; }
  __syncthreads();
  s = 0.f; ss = 0.f;
#pragma unroll
  for (int w = 0; w < 8; w++) { s += ra[w]; ss += rb[w]; }

  const float mean = s * (1.0f / CC);
  const float var  = ss * (1.0f / CC) - mean * mean;
  const float rstd = rsqrtf(var + 1e-5f);

  float4 gg = ((const float4*)g)[tid];
  float4 bb = ((const float4*)bt)[tid];
  float4 r;
  r.x = (v.x - mean) * rstd * gg.x + bb.x;
  r.y = (v.y - mean) * rstd * gg.y + bb.y;
  r.z = (v.z - mean) * rstd * gg.z + bb.z;
  r.w = (v.w - mean) * rstd * gg.w + bb.w;
  ((float4*)(o + (size_t)row * CC))[tid] = r;
}

// ---------------- masked softmax: one read, one write -----------------------
__global__ __launch_bounds__(256) void softmax_kernel(float* __restrict__ sc,
                                                      const int* __restrict__ seq_ls) {
  const int row = blockIdx.x;            // b*NH*T + h*T + q
  const int b   = row >> 14;             // / (NH*T)
  const int seq = seq_ls[b];
  float4* p = (float4*)(sc + (size_t)row * CT);
  const int tid = threadIdx.x;
  const int j0  = tid * 4;
  __shared__ float red[8];

  float4 v = p[tid];
  float m0 = (j0 + 0 < seq) ? v.x : -1e30f;
  float m1 = (j0 + 1 < seq) ? v.y : -1e30f;
  float m2 = (j0 + 2 < seq) ? v.z : -1e30f;
  float m3 = (j0 + 3 < seq) ? v.w : -1e30f;
  float m = fmaxf(fmaxf(m0, m1), fmaxf(m2, m3));
#pragma unroll
  for (int off = 16; off; off >>= 1) m = fmaxf(m, __shfl_xor_sync(0xFFFFFFFFu, m, off));
  if ((tid & 31) == 0) red[tid >> 5] = m;
  __syncthreads();
  m = red[0];
#pragma unroll
  for (int w = 1; w < 8; w++) m = fmaxf(m, red[w]);
  __syncthreads();

  float e0 = (j0 + 0 < seq) ? __expf(v.x - m) : 0.0f;
  float e1 = (j0 + 1 < seq) ? __expf(v.y - m) : 0.0f;
  float e2 = (j0 + 2 < seq) ? __expf(v.z - m) : 0.0f;
  float e3 = (j0 + 3 < seq) ? __expf(v.w - m) : 0.0f;
  float s = e0 + e1 + e2 + e3;
#pragma unroll
  for (int off = 16; off; off >>= 1) s += __shfl_xor_sync(0xFFFFFFFFu, s, off);
  if ((tid & 31) == 0) red[tid >> 5] = s;
  __syncthreads();
  s = 0.0f;
#pragma unroll
  for (int w = 0; w < 8; w++) s += red[w];
  const float inv = 1.0f / s;

  float4 r;
  r.x = e0 * inv; r.y = e1 * inv; r.z = e2 * inv; r.w = e3 * inv;
  p[tid] = r;
}

// ---------------- launch ----------------------------------------------------
static GP zero_gp() { GP p; memset(&p, 0, sizeof(p)); p.inner = 1; p.alpha = 1.0f; return p; }

extern "C" void kernel_launch(void* const* d_in, const int* in_sizes, int n_in,
                              void* d_out, int out_size) {
  (void)in_sizes; (void)n_in; (void)out_size;
  const float* x      = (const float*)d_in[0];
  const int*   seq_ls = (const int*)  d_in[1];
  const float* ln1_g  = (const float*)d_in[2];
  const float* ln1_b  = (const float*)d_in[3];
  const float* w_qkv  = (const float*)d_in[4];
  const float* b_qkv  = (const float*)d_in[5];
  const float* w_proj = (const float*)d_in[6];
  const float* b_proj = (const float*)d_in[7];
  const float* ln2_g  = (const float*)d_in[8];
  const float* ln2_b  = (const float*)d_in[9];
  const float* w_fc   = (const float*)d_in[10];
  const float* b_fc   = (const float*)d_in[11];
  const float* w_fc2  = (const float*)d_in[12];
  const float* b_fc2  = (const float*)d_in[13];
  float* out = (float*)d_out;

  float *h, *qkv, *sc, *y, *ff;
  cudaGetSymbolAddress((void**)&h,   g_h);
  cudaGetSymbolAddress((void**)&qkv, g_qkv);
  cudaGetSymbolAddress((void**)&sc,  g_scores);
  cudaGetSymbolAddress((void**)&y,   g_y);
  cudaGetSymbolAddress((void**)&ff,  g_ff);

  cudaFuncSetAttribute(gemm_tf32<0>, cudaFuncAttributeMaxDynamicSharedMemorySize, GEMM_SMEM_BYTES);
  cudaFuncSetAttribute(gemm_tf32<1>, cudaFuncAttributeMaxDynamicSharedMemorySize, GEMM_SMEM_BYTES);

  // 1) LN1
  ln_kernel<<<CM, 256>>>(x, ln1_g, ln1_b, h);

  // 2) QKV = h @ w_qkv + b_qkv
  {
    GP p = zero_gp();
    p.A = h;     p.lda = CC;
    p.B = w_qkv; p.ldb = 3 * CC;
    p.C = qkv;   p.ldc = 3 * CC;
    p.M = CM; p.N = 3 * CC; p.K = CC;
    p.bias = b_qkv;
    gemm_tf32<0><<<dim3(24, 64, 1), 256, GEMM_SMEM_BYTES>>>(p);
  }

  // 3) scores = (Q @ K^T) / 8   batched over (b,h)
  {
    GP p = zero_gp();
    p.A = qkv;      p.lda = 3 * CC; p.sAo = (long long)CT * 3 * CC; p.sAi = CHD;
    p.B = qkv + CC; p.ldb = 3 * CC; p.sBo = (long long)CT * 3 * CC; p.sBi = CHD;
    p.C = sc; p.ldc = CT; p.sCo = (long long)CNH * CT * CT; p.sCi = (long long)CT * CT;
    p.M = CT; p.N = CT; p.K = CHD;
    p.alpha = 0.125f;
    p.inner = CNH;
    gemm_tf32<1><<<dim3(8, 8, CB * CNH), 256, GEMM_SMEM_BYTES>>>(p);
  }

  // 4) masked softmax (in place)
  softmax_kernel<<<CB * CNH * CT, 256>>>(sc, seq_ls);

  // 5) Y = P @ V
  {
    GP p = zero_gp();
    p.A = sc;           p.lda = CT;     p.sAo = (long long)CNH * CT * CT; p.sAi = (long long)CT * CT;
    p.B = qkv + 2 * CC; p.ldb = 3 * CC; p.sBo = (long long)CT * 3 * CC;   p.sBi = CHD;
    p.C = y; p.ldc = CC; p.sCo = (long long)CT * CC; p.sCi = CHD;
    p.M = CT; p.N = CHD; p.K = CT;
    p.inner = CNH;
    gemm_tf32<0><<<dim3(1, 8, CB * CNH), 256, GEMM_SMEM_BYTES>>>(p);
  }

  // 6) x1 = x + Y @ w_proj + b_proj  -> out
  {
    GP p = zero_gp();
    p.A = y;      p.lda = CC;
    p.B = w_proj; p.ldb = CC;
    p.C = out;    p.ldc = CC;
    p.M = CM; p.N = CC; p.K = CC;
    p.bias = b_proj;
    p.R = x; p.ldr = CC;
    gemm_tf32<0><<<dim3(8, 64, 1), 256, GEMM_SMEM_BYTES>>>(p);
  }

  // 7) LN2
  ln_kernel<<<CM, 256>>>(out, ln2_g, ln2_b, h);

  // 8) ff = relu(h @ w_fc + b_fc)
  {
    GP p = zero_gp();
    p.A = h;    p.lda = CC;
    p.B = w_fc; p.ldb = CFF;
    p.C = ff;   p.ldc = CFF;
    p.M = CM; p.N = CFF; p.K = CC;
    p.bias = b_fc; p.relu = 1;
    gemm_tf32<0><<<dim3(32, 64, 1), 256, GEMM_SMEM_BYTES>>>(p);
  }

  // 9) out = out + ff @ w_fc2 + b_fc2
  {
    GP p = zero_gp();
    p.A = ff;    p.lda = CFF;
    p.B = w_fc2; p.ldb = CC;
    p.C = out;   p.ldc = CC;
    p.M = CM; p.N = CC; p.K = CFF;
    p.bias = b_fc2;
    p.R = out; p.ldr = CC;
    gemm_tf32<0><<<dim3(8, 64, 1), 256, GEMM_SMEM_BYTES>>>(p);
  }
}